// round 11
// baseline (speedup 1.0000x reference)
#include <cuda_runtime.h>
#include <cuda_fp16.h>
#include <math.h>
#include <stdint.h>

// Problem constants
#define T_TOK 8192
#define D_DIM 1024
#define FF_DIM 2048
#define E_NUM 8
#define K_TOP 2
#define NSLOT (T_TOK * K_TOP)
#define W1_LD (E_NUM * FF_DIM)

// ---------------- scratch (device globals) ---------------------------------
__device__ __half g_xh[(size_t)T_TOK * D_DIM];
__device__ __half g_w1h[(size_t)D_DIM * W1_LD];
__device__ __half g_w2h[(size_t)E_NUM * FF_DIM * D_DIM];
__device__ __half g_hh[(size_t)NSLOT * FF_DIM];

__device__ int   g_sel[NSLOT];
__device__ float g_wsel[NSLOT];
__device__ int   g_slot_token[NSLOT];
__device__ float g_slot_w[NSLOT];
__device__ int   g_counts[E_NUM];
__device__ int   g_offsets[E_NUM];
__device__ int   g_fill[E_NUM];
__device__ float g_psum[E_NUM];
__device__ float g_zsum;

// ---------------- convert kernels (f32 -> fp16 weights) --------------------
__global__ void cvt_w1_kernel(const float* __restrict__ src) {
    int n4 = (D_DIM * W1_LD) / 4;
    const float4* s4 = (const float4*)src;
    for (int i = blockIdx.x * blockDim.x + threadIdx.x; i < n4;
         i += gridDim.x * blockDim.x) {
        float4 v = s4[i];
        __half h[4];
        h[0] = __float2half_rn(v.x); h[1] = __float2half_rn(v.y);
        h[2] = __float2half_rn(v.z); h[3] = __float2half_rn(v.w);
        ((uint2*)g_w1h)[i] = *(uint2*)h;
    }
}
__global__ void cvt_w2_kernel(const float* __restrict__ src) {
    int n4 = (E_NUM * FF_DIM * D_DIM) / 4;
    const float4* s4 = (const float4*)src;
    for (int i = blockIdx.x * blockDim.x + threadIdx.x; i < n4;
         i += gridDim.x * blockDim.x) {
        float4 v = s4[i];
        __half h[4];
        h[0] = __float2half_rn(v.x); h[1] = __float2half_rn(v.y);
        h[2] = __float2half_rn(v.z); h[3] = __float2half_rn(v.w);
        ((uint2*)g_w2h)[i] = *(uint2*)h;
    }
}

// ---------------- kernel 0: zero output ----------------
__global__ void zero_out_kernel(float* out, int n) {
    int idx = blockIdx.x * blockDim.x + threadIdx.x;
    int stride = gridDim.x * blockDim.x;
    for (int i = idx; i < n; i += stride) out[i] = 0.0f;
}

// ---------------- kernel 1: init accumulators ----------------
__global__ void init_kernel() {
    int t = threadIdx.x;
    if (t < E_NUM) { g_counts[t] = 0; g_fill[t] = 0; g_psum[t] = 0.0f; }
    if (t == 0) g_zsum = 0.0f;
}

// ---------------- kernel 2: router (also emits fp16 x) ---------------------
__global__ __launch_bounds__(256) void router_kernel(
    const float* __restrict__ x, const float* __restrict__ rw)
{
    __shared__ float s_rw[E_NUM * D_DIM];
    __shared__ float sp[E_NUM];
    __shared__ int   sc[E_NUM];
    __shared__ float sz;

    int tid = threadIdx.x;
    for (int i = tid; i < E_NUM * D_DIM; i += 256) s_rw[i] = rw[i];
    if (tid < E_NUM) { sp[tid] = 0.0f; sc[tid] = 0; }
    if (tid == 0) sz = 0.0f;
    __syncthreads();

    int warp = tid >> 5;
    int lane = tid & 31;
    int t = blockIdx.x * 8 + warp;

    float acc[E_NUM];
#pragma unroll
    for (int e = 0; e < E_NUM; e++) acc[e] = 0.0f;

    const float* xr = x + (size_t)t * D_DIM;
    __half* xw = g_xh + (size_t)t * D_DIM;
    for (int d = lane; d < D_DIM; d += 32) {
        float xv = xr[d];
        xw[d] = __float2half_rn(xv);          // fused fp16 conversion
#pragma unroll
        for (int e = 0; e < E_NUM; e++) acc[e] += xv * s_rw[e * D_DIM + d];
    }
#pragma unroll
    for (int e = 0; e < E_NUM; e++) {
#pragma unroll
        for (int off = 16; off > 0; off >>= 1)
            acc[e] += __shfl_xor_sync(0xFFFFFFFF, acc[e], off);
    }

    if (lane == 0) {
        float m = acc[0];
#pragma unroll
        for (int e = 1; e < E_NUM; e++) m = fmaxf(m, acc[e]);
        float p[E_NUM], s = 0.0f;
#pragma unroll
        for (int e = 0; e < E_NUM; e++) { p[e] = expf(acc[e] - m); s += p[e]; }
        float inv = 1.0f / s;
        float lse = m + logf(s);

        int i1 = 0;
#pragma unroll
        for (int e = 1; e < E_NUM; e++) if (acc[e] > acc[i1]) i1 = e;
        int i2 = (i1 == 0) ? 1 : 0;
#pragma unroll
        for (int e = 0; e < E_NUM; e++)
            if (e != i1 && acc[e] > acc[i2]) i2 = e;

        float p1 = p[i1] * inv, p2 = p[i2] * inv;
        float winv = 1.0f / (p1 + p2);
        g_sel[2 * t]      = i1;
        g_wsel[2 * t]     = p1 * winv;
        g_sel[2 * t + 1]  = i2;
        g_wsel[2 * t + 1] = p2 * winv;

#pragma unroll
        for (int e = 0; e < E_NUM; e++) atomicAdd(&sp[e], p[e] * inv);
        atomicAdd(&sz, lse * lse);
        atomicAdd(&sc[i1], 1);
        atomicAdd(&sc[i2], 1);
    }
    __syncthreads();
    if (tid < E_NUM) {
        atomicAdd(&g_psum[tid], sp[tid]);
        atomicAdd(&g_counts[tid], sc[tid]);
    }
    if (tid == 0) atomicAdd(&g_zsum, sz);
}

// ---------------- kernel 3: finalize losses + offsets scan ----------------
__global__ void finalize_kernel(float* out, int out_size) {
    if (threadIdx.x == 0 && blockIdx.x == 0) {
        int off = 0;
        for (int e = 0; e < E_NUM; e++) { g_offsets[e] = off; off += g_counts[e]; }
        float z = g_zsum / (float)T_TOK;
        float lb = 0.0f;
        for (int e = 0; e < E_NUM; e++)
            lb += ((float)g_counts[e] / (float)(T_TOK * K_TOP)) *
                  (g_psum[e] / (float)T_TOK);
        lb *= (float)E_NUM;
        out[out_size - 2] = z;
        out[out_size - 1] = lb;
    }
}

// ---------------- kernel 4: scatter into expert groups ----------------
__global__ void scatter_kernel() {
    int s = blockIdx.x * blockDim.x + threadIdx.x;
    if (s >= NSLOT) return;
    int e = g_sel[s];
    int pos = g_offsets[e] + atomicAdd(&g_fill[e], 1);
    g_slot_token[pos] = s >> 1;
    g_slot_w[pos]     = g_wsel[s];
}

// ============== fp16 tensor-core grouped GEMMs (double-buffered) ===========
// Tile BM=128, BN=128, BK=32. 256 thr = 8 warps (2M x 4N), warp 64x32.
// 2 smem stages: iter reads stage s, stores stage s^1 -> ONE barrier/iter.
#define BM 128
#define BN 128
#define BKB 32
#define AKP 40    // A row stride (half): 80 B
#define BNP 136   // B row stride (half): 272 B

__device__ __forceinline__ float gelu_exact(float v) {
    return 0.5f * v * (1.0f + erff(v * 0.70710678118654752f));
}

__device__ __forceinline__ void mma_f16(
    float& c0, float& c1, float& c2, float& c3,
    uint32_t a0, uint32_t a1, uint32_t a2, uint32_t a3,
    uint32_t b0, uint32_t b1)
{
    asm volatile(
        "mma.sync.aligned.m16n8k16.row.col.f32.f16.f16.f32 "
        "{%0,%1,%2,%3}, {%4,%5,%6,%7}, {%8,%9}, {%0,%1,%2,%3};"
        : "+f"(c0), "+f"(c1), "+f"(c2), "+f"(c3)
        : "r"(a0), "r"(a1), "r"(a2), "r"(a3), "r"(b0), "r"(b1));
}

__device__ __forceinline__ void ldsm_x4(uint32_t* r, const void* p) {
    uint32_t addr = (uint32_t)__cvta_generic_to_shared(p);
    asm volatile("ldmatrix.sync.aligned.m8n8.x4.shared.b16 {%0,%1,%2,%3}, [%4];"
                 : "=r"(r[0]), "=r"(r[1]), "=r"(r[2]), "=r"(r[3]) : "r"(addr));
}
__device__ __forceinline__ void ldsm_x4_trans(uint32_t* r, const void* p) {
    uint32_t addr = (uint32_t)__cvta_generic_to_shared(p);
    asm volatile("ldmatrix.sync.aligned.m8n8.x4.trans.shared.b16 {%0,%1,%2,%3}, [%4];"
                 : "=r"(r[0]), "=r"(r[1]), "=r"(r[2]), "=r"(r[3]) : "r"(addr));
}

// GEMM1: h = gelu( x_gathered @ w1_e )   [slots x FF]
__global__ __launch_bounds__(256, 2) void gemm1_kernel() {
    int e = blockIdx.z;
    int base = g_offsets[e];
    int cnt  = g_counts[e];
    int m0   = blockIdx.y * BM;
    if (m0 >= cnt) return;
    int n0   = blockIdx.x * BN;

    __shared__ __half Ah[2][BM][AKP];
    __shared__ __half Bh[2][BKB][BNP];

    int tid  = threadIdx.x;
    int lane = tid & 31;
    int warp = tid >> 5;
    int group = lane >> 2;
    int tid4  = lane & 3;
    int wm = (warp & 1) * 64;
    int wn = (warp >> 1) * 32;
    int lrow = lane & 15;
    int lcol = (lane >> 4) << 3;

    int am = tid >> 1;
    int kb = (tid & 1) * 16;
    int arow = base + m0 + am;
    int tok  = g_slot_token[arow < NSLOT ? arow : NSLOT - 1];
    const __half* aph = g_xh + (size_t)tok * D_DIM + kb;

    int bkr = tid >> 3;
    int bnc = (tid & 7) * 16;
    size_t bbase = (size_t)e * FF_DIM + n0 + bnc;

    float acc[4][4][4];
#pragma unroll
    for (int mi = 0; mi < 4; mi++)
#pragma unroll
        for (int ni = 0; ni < 4; ni++)
#pragma unroll
            for (int c = 0; c < 4; c++) acc[mi][ni][c] = 0.0f;

    // prologue: fill stage 0
    {
        uint4 a0 = *(const uint4*)(aph + 0);
        uint4 a1 = *(const uint4*)(aph + 8);
        uint4 b0 = *(const uint4*)(g_w1h + (size_t)bkr * W1_LD + bbase);
        uint4 b1 = *(const uint4*)(g_w1h + (size_t)bkr * W1_LD + bbase + 8);
        *(uint4*)&Ah[0][am][kb]     = a0; *(uint4*)&Ah[0][am][kb + 8]   = a1;
        *(uint4*)&Bh[0][bkr][bnc]   = b0; *(uint4*)&Bh[0][bkr][bnc + 8] = b1;
    }
    __syncthreads();

    int s = 0;
    for (int kt = 0; kt < D_DIM; kt += BKB) {
        bool more = (kt + BKB) < D_DIM;
        uint4 pa0, pa1, pb0, pb1;
        if (more) {
            pa0 = *(const uint4*)(aph + kt + BKB + 0);
            pa1 = *(const uint4*)(aph + kt + BKB + 8);
            pb0 = *(const uint4*)(g_w1h + (size_t)(kt + BKB + bkr) * W1_LD + bbase);
            pb1 = *(const uint4*)(g_w1h + (size_t)(kt + BKB + bkr) * W1_LD + bbase + 8);
        }
#pragma unroll
        for (int ks = 0; ks < 2; ks++) {
            int k0 = ks * 16;
            uint32_t ah[4][4], bh[4][2];
#pragma unroll
            for (int mi = 0; mi < 4; mi++)
                ldsm_x4(ah[mi], &Ah[s][wm + mi * 16 + lrow][k0 + lcol]);
#pragma unroll
            for (int nh = 0; nh < 2; nh++) {
                uint32_t r[4];
                ldsm_x4_trans(r, &Bh[s][k0 + lrow][wn + nh * 16 + lcol]);
                bh[2 * nh][0] = r[0]; bh[2 * nh][1] = r[1];
                bh[2 * nh + 1][0] = r[2]; bh[2 * nh + 1][1] = r[3];
            }
#pragma unroll
            for (int mi = 0; mi < 4; mi++)
#pragma unroll
                for (int ni = 0; ni < 4; ni++)
                    mma_f16(acc[mi][ni][0], acc[mi][ni][1], acc[mi][ni][2], acc[mi][ni][3],
                            ah[mi][0], ah[mi][1], ah[mi][2], ah[mi][3],
                            bh[ni][0], bh[ni][1]);
        }
        if (more) {
            int d = s ^ 1;
            *(uint4*)&Ah[d][am][kb]     = pa0; *(uint4*)&Ah[d][am][kb + 8]   = pa1;
            *(uint4*)&Bh[d][bkr][bnc]   = pb0; *(uint4*)&Bh[d][bkr][bnc + 8] = pb1;
        }
        __syncthreads();
        s ^= 1;
    }

    // epilogue: gelu -> fp16 -> g_hh
#pragma unroll
    for (int mi = 0; mi < 4; mi++) {
        int rm0 = m0 + wm + mi * 16 + group;
        int rm1 = rm0 + 8;
#pragma unroll
        for (int ni = 0; ni < 4; ni++) {
            int n = n0 + wn + ni * 8 + tid4 * 2;
            if (rm0 < cnt) {
                __half h0 = __float2half_rn(gelu_exact(acc[mi][ni][0]));
                __half h1 = __float2half_rn(gelu_exact(acc[mi][ni][1]));
                *(__half2*)(g_hh + (size_t)(base + rm0) * FF_DIM + n) =
                    __halves2half2(h0, h1);
            }
            if (rm1 < cnt) {
                __half h0 = __float2half_rn(gelu_exact(acc[mi][ni][2]));
                __half h1 = __float2half_rn(gelu_exact(acc[mi][ni][3]));
                *(__half2*)(g_hh + (size_t)(base + rm1) * FF_DIM + n) =
                    __halves2half2(h0, h1);
            }
        }
    }
}

// GEMM2: out[tok(row)] += w(row) * ( h[row] @ w2_e )
__global__ __launch_bounds__(256, 2) void gemm2_kernel(float* __restrict__ out) {
    int e = blockIdx.z;
    int base = g_offsets[e];
    int cnt  = g_counts[e];
    int m0   = blockIdx.y * BM;
    if (m0 >= cnt) return;
    int n0   = blockIdx.x * BN;

    __shared__ __half Ah[2][BM][AKP];
    __shared__ __half Bh[2][BKB][BNP];

    int tid  = threadIdx.x;
    int lane = tid & 31;
    int warp = tid >> 5;
    int group = lane >> 2;
    int tid4  = lane & 3;
    int wm = (warp & 1) * 64;
    int wn = (warp >> 1) * 32;
    int lrow = lane & 15;
    int lcol = (lane >> 4) << 3;

    int am = tid >> 1;
    int kb = (tid & 1) * 16;
    int arow = base + m0 + am;
    if (arow >= NSLOT) arow = NSLOT - 1;
    const __half* aph = g_hh + (size_t)arow * FF_DIM + kb;

    int bkr = tid >> 3;
    int bnc = (tid & 7) * 16;
    size_t bbase = (size_t)e * FF_DIM * D_DIM + n0 + bnc;

    float acc[4][4][4];
#pragma unroll
    for (int mi = 0; mi < 4; mi++)
#pragma unroll
        for (int ni = 0; ni < 4; ni++)
#pragma unroll
            for (int c = 0; c < 4; c++) acc[mi][ni][c] = 0.0f;

    {
        uint4 a0 = *(const uint4*)(aph + 0);
        uint4 a1 = *(const uint4*)(aph + 8);
        uint4 b0 = *(const uint4*)(g_w2h + (size_t)bkr * D_DIM + bbase);
        uint4 b1 = *(const uint4*)(g_w2h + (size_t)bkr * D_DIM + bbase + 8);
        *(uint4*)&Ah[0][am][kb]     = a0; *(uint4*)&Ah[0][am][kb + 8]   = a1;
        *(uint4*)&Bh[0][bkr][bnc]   = b0; *(uint4*)&Bh[0][bkr][bnc + 8] = b1;
    }
    __syncthreads();

    int s = 0;
    for (int kt = 0; kt < FF_DIM; kt += BKB) {
        bool more = (kt + BKB) < FF_DIM;
        uint4 pa0, pa1, pb0, pb1;
        if (more) {
            pa0 = *(const uint4*)(aph + kt + BKB + 0);
            pa1 = *(const uint4*)(aph + kt + BKB + 8);
            pb0 = *(const uint4*)(g_w2h + (size_t)(kt + BKB + bkr) * D_DIM + bbase);
            pb1 = *(const uint4*)(g_w2h + (size_t)(kt + BKB + bkr) * D_DIM + bbase + 8);
        }
#pragma unroll
        for (int ks = 0; ks < 2; ks++) {
            int k0 = ks * 16;
            uint32_t ah[4][4], bh[4][2];
#pragma unroll
            for (int mi = 0; mi < 4; mi++)
                ldsm_x4(ah[mi], &Ah[s][wm + mi * 16 + lrow][k0 + lcol]);
#pragma unroll
            for (int nh = 0; nh < 2; nh++) {
                uint32_t r[4];
                ldsm_x4_trans(r, &Bh[s][k0 + lrow][wn + nh * 16 + lcol]);
                bh[2 * nh][0] = r[0]; bh[2 * nh][1] = r[1];
                bh[2 * nh + 1][0] = r[2]; bh[2 * nh + 1][1] = r[3];
            }
#pragma unroll
            for (int mi = 0; mi < 4; mi++)
#pragma unroll
                for (int ni = 0; ni < 4; ni++)
                    mma_f16(acc[mi][ni][0], acc[mi][ni][1], acc[mi][ni][2], acc[mi][ni][3],
                            ah[mi][0], ah[mi][1], ah[mi][2], ah[mi][3],
                            bh[ni][0], bh[ni][1]);
        }
        if (more) {
            int d = s ^ 1;
            *(uint4*)&Ah[d][am][kb]     = pa0; *(uint4*)&Ah[d][am][kb + 8]   = pa1;
            *(uint4*)&Bh[d][bkr][bnc]   = pb0; *(uint4*)&Bh[d][bkr][bnc + 8] = pb1;
        }
        __syncthreads();
        s ^= 1;
    }

    // epilogue: weighted atomic scatter
#pragma unroll
    for (int mi = 0; mi < 4; mi++) {
        int rm0 = m0 + wm + mi * 16 + group;
        int rm1 = rm0 + 8;
        int r0 = base + rm0, r1 = base + rm1;
        int tok0 = 0, tok1 = 0; float w0 = 0.f, w1v = 0.f;
        if (rm0 < cnt) { tok0 = g_slot_token[r0]; w0 = g_slot_w[r0]; }
        if (rm1 < cnt) { tok1 = g_slot_token[r1]; w1v = g_slot_w[r1]; }
#pragma unroll
        for (int ni = 0; ni < 4; ni++) {
            int n = n0 + wn + ni * 8 + tid4 * 2;
            if (rm0 < cnt) {
                float* op = out + (size_t)tok0 * D_DIM + n;
                atomicAdd(op + 0, w0 * acc[mi][ni][0]);
                atomicAdd(op + 1, w0 * acc[mi][ni][1]);
            }
            if (rm1 < cnt) {
                float* op = out + (size_t)tok1 * D_DIM + n;
                atomicAdd(op + 0, w1v * acc[mi][ni][2]);
                atomicAdd(op + 1, w1v * acc[mi][ni][3]);
            }
        }
    }
}

// ---------------- launcher ----------------
extern "C" void kernel_launch(void* const* d_in, const int* in_sizes, int n_in,
                              void* d_out, int out_size) {
    const float* x  = (const float*)d_in[0];
    const float* rw = (const float*)d_in[1];
    const float* w1 = (const float*)d_in[2];
    const float* w2 = (const float*)d_in[3];
    float* out = (float*)d_out;

    zero_out_kernel<<<1024, 256>>>(out, out_size);
    init_kernel<<<1, 64>>>();
    cvt_w1_kernel<<<4096, 256>>>(w1);
    cvt_w2_kernel<<<4096, 256>>>(w2);
    router_kernel<<<T_TOK / 8, 256>>>(x, rw);
    finalize_kernel<<<1, 32>>>(out, out_size);
    scatter_kernel<<<NSLOT / 256, 256>>>();

    dim3 g1(FF_DIM / BN, NSLOT / BM, E_NUM);
    gemm1_kernel<<<g1, 256>>>();
    dim3 g2(D_DIM / BN, NSLOT / BM, E_NUM);
    gemm2_kernel<<<g2, 256>>>(out);
}

// round 12
// speedup vs baseline: 1.0145x; 1.0145x over previous
#include <cuda_runtime.h>
#include <cuda_fp16.h>
#include <math.h>
#include <stdint.h>

// Problem constants
#define T_TOK 8192
#define D_DIM 1024
#define FF_DIM 2048
#define E_NUM 8
#define K_TOP 2
#define NSLOT (T_TOK * K_TOP)
#define W1_LD (E_NUM * FF_DIM)

// ---------------- scratch (device globals) ---------------------------------
__device__ __half g_xh[(size_t)T_TOK * D_DIM];
__device__ __half g_w1h[(size_t)D_DIM * W1_LD];
__device__ __half g_w2h[(size_t)E_NUM * FF_DIM * D_DIM];
__device__ __half g_hh[(size_t)NSLOT * FF_DIM];

__device__ int   g_sel[NSLOT];
__device__ float g_wsel[NSLOT];
__device__ int   g_slot_token[NSLOT];
__device__ float g_slot_w[NSLOT];
__device__ int   g_counts[E_NUM];
__device__ int   g_offsets[E_NUM];
__device__ int   g_fill[E_NUM];
__device__ float g_psum[E_NUM];
__device__ float g_zsum;

// ---------------- merged weight convert (f32 -> fp16) ----------------------
__global__ void cvt_w_kernel(const float* __restrict__ w1,
                             const float* __restrict__ w2) {
    const int n1 = (D_DIM * W1_LD) / 4;
    const int n2 = (E_NUM * FF_DIM * D_DIM) / 4;
    for (int i = blockIdx.x * blockDim.x + threadIdx.x; i < n1 + n2;
         i += gridDim.x * blockDim.x) {
        float4 v;
        if (i < n1) v = ((const float4*)w1)[i];
        else        v = ((const float4*)w2)[i - n1];
        __half h[4];
        h[0] = __float2half_rn(v.x); h[1] = __float2half_rn(v.y);
        h[2] = __float2half_rn(v.z); h[3] = __float2half_rn(v.w);
        if (i < n1) ((uint2*)g_w1h)[i]      = *(uint2*)h;
        else        ((uint2*)g_w2h)[i - n1] = *(uint2*)h;
    }
}

// ---------------- kernel 0: zero output ----------------
__global__ void zero_out_kernel(float* out, int n) {
    int idx = blockIdx.x * blockDim.x + threadIdx.x;
    int stride = gridDim.x * blockDim.x;
    for (int i = idx; i < n; i += stride) out[i] = 0.0f;
}

// ---------------- kernel 1: init accumulators ----------------
__global__ void init_kernel() {
    int t = threadIdx.x;
    if (t < E_NUM) { g_counts[t] = 0; g_fill[t] = 0; g_psum[t] = 0.0f; }
    if (t == 0) g_zsum = 0.0f;
}

// ---------------- kernel 2: router (also emits fp16 x) ---------------------
__global__ __launch_bounds__(256) void router_kernel(
    const float* __restrict__ x, const float* __restrict__ rw)
{
    __shared__ float s_rw[E_NUM * D_DIM];
    __shared__ float sp[E_NUM];
    __shared__ int   sc[E_NUM];
    __shared__ float sz;

    int tid = threadIdx.x;
    for (int i = tid; i < E_NUM * D_DIM; i += 256) s_rw[i] = rw[i];
    if (tid < E_NUM) { sp[tid] = 0.0f; sc[tid] = 0; }
    if (tid == 0) sz = 0.0f;
    __syncthreads();

    int warp = tid >> 5;
    int lane = tid & 31;
    int t = blockIdx.x * 8 + warp;

    float acc[E_NUM];
#pragma unroll
    for (int e = 0; e < E_NUM; e++) acc[e] = 0.0f;

    const float* xr = x + (size_t)t * D_DIM;
    __half* xw = g_xh + (size_t)t * D_DIM;
    for (int d = lane; d < D_DIM; d += 32) {
        float xv = xr[d];
        xw[d] = __float2half_rn(xv);
#pragma unroll
        for (int e = 0; e < E_NUM; e++) acc[e] += xv * s_rw[e * D_DIM + d];
    }
#pragma unroll
    for (int e = 0; e < E_NUM; e++) {
#pragma unroll
        for (int off = 16; off > 0; off >>= 1)
            acc[e] += __shfl_xor_sync(0xFFFFFFFF, acc[e], off);
    }

    if (lane == 0) {
        float m = acc[0];
#pragma unroll
        for (int e = 1; e < E_NUM; e++) m = fmaxf(m, acc[e]);
        float p[E_NUM], s = 0.0f;
#pragma unroll
        for (int e = 0; e < E_NUM; e++) { p[e] = expf(acc[e] - m); s += p[e]; }
        float inv = 1.0f / s;
        float lse = m + logf(s);

        int i1 = 0;
#pragma unroll
        for (int e = 1; e < E_NUM; e++) if (acc[e] > acc[i1]) i1 = e;
        int i2 = (i1 == 0) ? 1 : 0;
#pragma unroll
        for (int e = 0; e < E_NUM; e++)
            if (e != i1 && acc[e] > acc[i2]) i2 = e;

        float p1 = p[i1] * inv, p2 = p[i2] * inv;
        float winv = 1.0f / (p1 + p2);
        g_sel[2 * t]      = i1;
        g_wsel[2 * t]     = p1 * winv;
        g_sel[2 * t + 1]  = i2;
        g_wsel[2 * t + 1] = p2 * winv;

#pragma unroll
        for (int e = 0; e < E_NUM; e++) atomicAdd(&sp[e], p[e] * inv);
        atomicAdd(&sz, lse * lse);
        atomicAdd(&sc[i1], 1);
        atomicAdd(&sc[i2], 1);
    }
    __syncthreads();
    if (tid < E_NUM) {
        atomicAdd(&g_psum[tid], sp[tid]);
        atomicAdd(&g_counts[tid], sc[tid]);
    }
    if (tid == 0) atomicAdd(&g_zsum, sz);
}

// ---------------- kernel 3: finalize losses + offsets scan ----------------
__global__ void finalize_kernel(float* out, int out_size) {
    if (threadIdx.x == 0 && blockIdx.x == 0) {
        int off = 0;
        for (int e = 0; e < E_NUM; e++) { g_offsets[e] = off; off += g_counts[e]; }
        float z = g_zsum / (float)T_TOK;
        float lb = 0.0f;
        for (int e = 0; e < E_NUM; e++)
            lb += ((float)g_counts[e] / (float)(T_TOK * K_TOP)) *
                  (g_psum[e] / (float)T_TOK);
        lb *= (float)E_NUM;
        out[out_size - 2] = z;
        out[out_size - 1] = lb;
    }
}

// ---------------- kernel 4: scatter into expert groups ----------------
__global__ void scatter_kernel() {
    int s = blockIdx.x * blockDim.x + threadIdx.x;
    if (s >= NSLOT) return;
    int e = g_sel[s];
    int pos = g_offsets[e] + atomicAdd(&g_fill[e], 1);
    g_slot_token[pos] = s >> 1;
    g_slot_w[pos]     = g_wsel[s];
}

// ============== fp16 tensor-core grouped GEMMs =============================
// BM=128, BN=128, BK=32. 8 warps (2M x 4N), warp 64x32, m16n8k16 f16.
// Static double buffer (two named stage arrays), K-loop unrolled by 2:
// one barrier per 32-K stage, all smem addresses compile-time.
#define BM 128
#define BN 128
#define BKB 32
#define AKP 40
#define BNP 136

__device__ __forceinline__ float gelu_exact(float v) {
    return 0.5f * v * (1.0f + erff(v * 0.70710678118654752f));
}

__device__ __forceinline__ void mma_f16(
    float& c0, float& c1, float& c2, float& c3,
    uint32_t a0, uint32_t a1, uint32_t a2, uint32_t a3,
    uint32_t b0, uint32_t b1)
{
    asm volatile(
        "mma.sync.aligned.m16n8k16.row.col.f32.f16.f16.f32 "
        "{%0,%1,%2,%3}, {%4,%5,%6,%7}, {%8,%9}, {%0,%1,%2,%3};"
        : "+f"(c0), "+f"(c1), "+f"(c2), "+f"(c3)
        : "r"(a0), "r"(a1), "r"(a2), "r"(a3), "r"(b0), "r"(b1));
}

__device__ __forceinline__ void ldsm_x4(uint32_t* r, const void* p) {
    uint32_t addr = (uint32_t)__cvta_generic_to_shared(p);
    asm volatile("ldmatrix.sync.aligned.m8n8.x4.shared.b16 {%0,%1,%2,%3}, [%4];"
                 : "=r"(r[0]), "=r"(r[1]), "=r"(r[2]), "=r"(r[3]) : "r"(addr));
}
__device__ __forceinline__ void ldsm_x4_trans(uint32_t* r, const void* p) {
    uint32_t addr = (uint32_t)__cvta_generic_to_shared(p);
    asm volatile("ldmatrix.sync.aligned.m8n8.x4.trans.shared.b16 {%0,%1,%2,%3}, [%4];"
                 : "=r"(r[0]), "=r"(r[1]), "=r"(r[2]), "=r"(r[3]) : "r"(addr));
}

// MMA over one 32-K stage held in (AH, BH)
#define MMA_STAGE(AH, BH)                                                      \
    do {                                                                       \
        _Pragma("unroll")                                                      \
        for (int ks = 0; ks < 2; ks++) {                                       \
            int k0 = ks * 16;                                                  \
            uint32_t ah[4][4], bh[4][2];                                       \
            _Pragma("unroll")                                                  \
            for (int mi = 0; mi < 4; mi++)                                     \
                ldsm_x4(ah[mi], &AH[wm + mi * 16 + lrow][k0 + lcol]);          \
            _Pragma("unroll")                                                  \
            for (int nh = 0; nh < 2; nh++) {                                   \
                uint32_t r[4];                                                 \
                ldsm_x4_trans(r, &BH[k0 + lrow][wn + nh * 16 + lcol]);         \
                bh[2 * nh][0] = r[0]; bh[2 * nh][1] = r[1];                    \
                bh[2 * nh + 1][0] = r[2]; bh[2 * nh + 1][1] = r[3];            \
            }                                                                  \
            _Pragma("unroll")                                                  \
            for (int mi = 0; mi < 4; mi++)                                     \
                _Pragma("unroll")                                              \
                for (int ni = 0; ni < 4; ni++)                                 \
                    mma_f16(acc[mi][ni][0], acc[mi][ni][1],                    \
                            acc[mi][ni][2], acc[mi][ni][3],                    \
                            ah[mi][0], ah[mi][1], ah[mi][2], ah[mi][3],        \
                            bh[ni][0], bh[ni][1]);                             \
        }                                                                      \
    } while (0)

#define STS_STAGE(AH, BH)                                                      \
    do {                                                                       \
        *(uint4*)&AH[am][kb]     = pa0; *(uint4*)&AH[am][kb + 8]   = pa1;      \
        *(uint4*)&BH[bkr][bnc]   = pb0; *(uint4*)&BH[bkr][bnc + 8] = pb1;      \
    } while (0)

// GEMM1: h = gelu( x_gathered @ w1_e )
__global__ __launch_bounds__(256, 2) void gemm1_kernel() {
    int e = blockIdx.z;
    int base = g_offsets[e];
    int cnt  = g_counts[e];
    int m0   = blockIdx.y * BM;
    if (m0 >= cnt) return;
    int n0   = blockIdx.x * BN;

    __shared__ __half Ah0[BM][AKP], Ah1[BM][AKP];
    __shared__ __half Bh0[BKB][BNP], Bh1[BKB][BNP];

    int tid  = threadIdx.x;
    int lane = tid & 31;
    int warp = tid >> 5;
    int group = lane >> 2;
    int tid4  = lane & 3;
    int wm = (warp & 1) * 64;
    int wn = (warp >> 1) * 32;
    int lrow = lane & 15;
    int lcol = (lane >> 4) << 3;

    int am = tid >> 1;
    int kb = (tid & 1) * 16;
    int arow = base + m0 + am;
    int tok  = g_slot_token[arow < NSLOT ? arow : NSLOT - 1];
    const __half* aph = g_xh + (size_t)tok * D_DIM + kb;

    int bkr = tid >> 3;
    int bnc = (tid & 7) * 16;
    size_t bbase = (size_t)e * FF_DIM + n0 + bnc;

    float acc[4][4][4];
#pragma unroll
    for (int mi = 0; mi < 4; mi++)
#pragma unroll
        for (int ni = 0; ni < 4; ni++)
#pragma unroll
            for (int c = 0; c < 4; c++) acc[mi][ni][c] = 0.0f;

    uint4 pa0, pa1, pb0, pb1;
    // prologue: fill stage 0
    pa0 = *(const uint4*)(aph + 0);
    pa1 = *(const uint4*)(aph + 8);
    pb0 = *(const uint4*)(g_w1h + (size_t)bkr * W1_LD + bbase);
    pb1 = *(const uint4*)(g_w1h + (size_t)bkr * W1_LD + bbase + 8);
    STS_STAGE(Ah0, Bh0);
    __syncthreads();

#pragma unroll 1
    for (int kt = 0; kt < D_DIM; kt += 2 * BKB) {
        // half A: consume stage0; prefetch kt+32 (always valid: D_DIM % 64 == 0)
        pa0 = *(const uint4*)(aph + kt + BKB + 0);
        pa1 = *(const uint4*)(aph + kt + BKB + 8);
        pb0 = *(const uint4*)(g_w1h + (size_t)(kt + BKB + bkr) * W1_LD + bbase);
        pb1 = *(const uint4*)(g_w1h + (size_t)(kt + BKB + bkr) * W1_LD + bbase + 8);
        MMA_STAGE(Ah0, Bh0);
        STS_STAGE(Ah1, Bh1);
        __syncthreads();
        // half B: consume stage1; prefetch kt+64 if valid
        bool more = (kt + 2 * BKB) < D_DIM;
        if (more) {
            pa0 = *(const uint4*)(aph + kt + 2 * BKB + 0);
            pa1 = *(const uint4*)(aph + kt + 2 * BKB + 8);
            pb0 = *(const uint4*)(g_w1h + (size_t)(kt + 2 * BKB + bkr) * W1_LD + bbase);
            pb1 = *(const uint4*)(g_w1h + (size_t)(kt + 2 * BKB + bkr) * W1_LD + bbase + 8);
        }
        MMA_STAGE(Ah1, Bh1);
        if (more) STS_STAGE(Ah0, Bh0);
        __syncthreads();
    }

    // epilogue: gelu -> fp16 -> g_hh
#pragma unroll
    for (int mi = 0; mi < 4; mi++) {
        int rm0 = m0 + wm + mi * 16 + group;
        int rm1 = rm0 + 8;
#pragma unroll
        for (int ni = 0; ni < 4; ni++) {
            int n = n0 + wn + ni * 8 + tid4 * 2;
            if (rm0 < cnt) {
                __half h0 = __float2half_rn(gelu_exact(acc[mi][ni][0]));
                __half h1 = __float2half_rn(gelu_exact(acc[mi][ni][1]));
                *(__half2*)(g_hh + (size_t)(base + rm0) * FF_DIM + n) =
                    __halves2half2(h0, h1);
            }
            if (rm1 < cnt) {
                __half h0 = __float2half_rn(gelu_exact(acc[mi][ni][2]));
                __half h1 = __float2half_rn(gelu_exact(acc[mi][ni][3]));
                *(__half2*)(g_hh + (size_t)(base + rm1) * FF_DIM + n) =
                    __halves2half2(h0, h1);
            }
        }
    }
}

// GEMM2: out[tok(row)] += w(row) * ( h[row] @ w2_e )
__global__ __launch_bounds__(256, 2) void gemm2_kernel(float* __restrict__ out) {
    int e = blockIdx.z;
    int base = g_offsets[e];
    int cnt  = g_counts[e];
    int m0   = blockIdx.y * BM;
    if (m0 >= cnt) return;
    int n0   = blockIdx.x * BN;

    __shared__ __half Ah0[BM][AKP], Ah1[BM][AKP];
    __shared__ __half Bh0[BKB][BNP], Bh1[BKB][BNP];

    int tid  = threadIdx.x;
    int lane = tid & 31;
    int warp = tid >> 5;
    int group = lane >> 2;
    int tid4  = lane & 3;
    int wm = (warp & 1) * 64;
    int wn = (warp >> 1) * 32;
    int lrow = lane & 15;
    int lcol = (lane >> 4) << 3;

    int am = tid >> 1;
    int kb = (tid & 1) * 16;
    int arow = base + m0 + am;
    if (arow >= NSLOT) arow = NSLOT - 1;
    const __half* aph = g_hh + (size_t)arow * FF_DIM + kb;

    int bkr = tid >> 3;
    int bnc = (tid & 7) * 16;
    size_t bbase = (size_t)e * FF_DIM * D_DIM + n0 + bnc;

    float acc[4][4][4];
#pragma unroll
    for (int mi = 0; mi < 4; mi++)
#pragma unroll
        for (int ni = 0; ni < 4; ni++)
#pragma unroll
            for (int c = 0; c < 4; c++) acc[mi][ni][c] = 0.0f;

    uint4 pa0, pa1, pb0, pb1;
    pa0 = *(const uint4*)(aph + 0);
    pa1 = *(const uint4*)(aph + 8);
    pb0 = *(const uint4*)(g_w2h + (size_t)bkr * D_DIM + bbase);
    pb1 = *(const uint4*)(g_w2h + (size_t)bkr * D_DIM + bbase + 8);
    STS_STAGE(Ah0, Bh0);
    __syncthreads();

#pragma unroll 1
    for (int kt = 0; kt < FF_DIM; kt += 2 * BKB) {
        pa0 = *(const uint4*)(aph + kt + BKB + 0);
        pa1 = *(const uint4*)(aph + kt + BKB + 8);
        pb0 = *(const uint4*)(g_w2h + (size_t)(kt + BKB + bkr) * D_DIM + bbase);
        pb1 = *(const uint4*)(g_w2h + (size_t)(kt + BKB + bkr) * D_DIM + bbase + 8);
        MMA_STAGE(Ah0, Bh0);
        STS_STAGE(Ah1, Bh1);
        __syncthreads();
        bool more = (kt + 2 * BKB) < FF_DIM;
        if (more) {
            pa0 = *(const uint4*)(aph + kt + 2 * BKB + 0);
            pa1 = *(const uint4*)(aph + kt + 2 * BKB + 8);
            pb0 = *(const uint4*)(g_w2h + (size_t)(kt + 2 * BKB + bkr) * D_DIM + bbase);
            pb1 = *(const uint4*)(g_w2h + (size_t)(kt + 2 * BKB + bkr) * D_DIM + bbase + 8);
        }
        MMA_STAGE(Ah1, Bh1);
        if (more) STS_STAGE(Ah0, Bh0);
        __syncthreads();
    }

    // epilogue: weighted atomic scatter
#pragma unroll
    for (int mi = 0; mi < 4; mi++) {
        int rm0 = m0 + wm + mi * 16 + group;
        int rm1 = rm0 + 8;
        int r0 = base + rm0, r1 = base + rm1;
        int tok0 = 0, tok1 = 0; float w0 = 0.f, w1v = 0.f;
        if (rm0 < cnt) { tok0 = g_slot_token[r0]; w0 = g_slot_w[r0]; }
        if (rm1 < cnt) { tok1 = g_slot_token[r1]; w1v = g_slot_w[r1]; }
#pragma unroll
        for (int ni = 0; ni < 4; ni++) {
            int n = n0 + wn + ni * 8 + tid4 * 2;
            if (rm0 < cnt) {
                float* op = out + (size_t)tok0 * D_DIM + n;
                atomicAdd(op + 0, w0 * acc[mi][ni][0]);
                atomicAdd(op + 1, w0 * acc[mi][ni][1]);
            }
            if (rm1 < cnt) {
                float* op = out + (size_t)tok1 * D_DIM + n;
                atomicAdd(op + 0, w1v * acc[mi][ni][2]);
                atomicAdd(op + 1, w1v * acc[mi][ni][3]);
            }
        }
    }
}

// ---------------- launcher ----------------
extern "C" void kernel_launch(void* const* d_in, const int* in_sizes, int n_in,
                              void* d_out, int out_size) {
    const float* x  = (const float*)d_in[0];
    const float* rw = (const float*)d_in[1];
    const float* w1 = (const float*)d_in[2];
    const float* w2 = (const float*)d_in[3];
    float* out = (float*)d_out;

    zero_out_kernel<<<1024, 256>>>(out, out_size);
    init_kernel<<<1, 64>>>();
    cvt_w_kernel<<<8192, 256>>>(w1, w2);
    router_kernel<<<T_TOK / 8, 256>>>(x, rw);
    finalize_kernel<<<1, 32>>>(out, out_size);
    scatter_kernel<<<NSLOT / 256, 256>>>();

    // per-expert count is bounded by T_TOK, not NSLOT -> grid.y = 64
    dim3 g1(FF_DIM / BN, T_TOK / BM, E_NUM);
    gemm1_kernel<<<g1, 256>>>();
    dim3 g2(D_DIM / BN, T_TOK / BM, E_NUM);
    gemm2_kernel<<<g2, 256>>>(out);
}

// round 13
// speedup vs baseline: 1.0670x; 1.0517x over previous
#include <cuda_runtime.h>
#include <cuda_fp16.h>
#include <math.h>
#include <stdint.h>

// Problem constants
#define T_TOK 8192
#define D_DIM 1024
#define FF_DIM 2048
#define E_NUM 8
#define K_TOP 2
#define NSLOT (T_TOK * K_TOP)
#define W1_LD (E_NUM * FF_DIM)

// ---------------- scratch (device globals) ---------------------------------
__device__ __half g_xh[(size_t)T_TOK * D_DIM];
__device__ __half g_w1h[(size_t)D_DIM * W1_LD];
__device__ __half g_w2h[(size_t)E_NUM * FF_DIM * D_DIM];
__device__ __half g_hh[(size_t)NSLOT * FF_DIM];
__device__ float  g_y[(size_t)NSLOT * D_DIM];     // per-slot GEMM2 result

__device__ int   g_sel[NSLOT];
__device__ float g_wsel[NSLOT];
__device__ int   g_slot_token[NSLOT];
__device__ int   g_pos[NSLOT];                    // slot s -> grouped position
__device__ int   g_counts[E_NUM];
__device__ int   g_offsets[E_NUM];
__device__ int   g_fill[E_NUM];
__device__ float g_psum[E_NUM];
__device__ float g_zsum;

// ---------------- merged weight convert (f32 -> fp16) ----------------------
__global__ void cvt_w_kernel(const float* __restrict__ w1,
                             const float* __restrict__ w2) {
    const int n1 = (D_DIM * W1_LD) / 4;
    const int n2 = (E_NUM * FF_DIM * D_DIM) / 4;
    for (int i = blockIdx.x * blockDim.x + threadIdx.x; i < n1 + n2;
         i += gridDim.x * blockDim.x) {
        float4 v;
        if (i < n1) v = ((const float4*)w1)[i];
        else        v = ((const float4*)w2)[i - n1];
        __half h[4];
        h[0] = __float2half_rn(v.x); h[1] = __float2half_rn(v.y);
        h[2] = __float2half_rn(v.z); h[3] = __float2half_rn(v.w);
        if (i < n1) ((uint2*)g_w1h)[i]      = *(uint2*)h;
        else        ((uint2*)g_w2h)[i - n1] = *(uint2*)h;
    }
}

// ---------------- init accumulators ----------------
__global__ void init_kernel() {
    int t = threadIdx.x;
    if (t < E_NUM) { g_counts[t] = 0; g_fill[t] = 0; g_psum[t] = 0.0f; }
    if (t == 0) g_zsum = 0.0f;
}

// ---------------- router (also emits fp16 x) ---------------------
__global__ __launch_bounds__(256) void router_kernel(
    const float* __restrict__ x, const float* __restrict__ rw)
{
    __shared__ float s_rw[E_NUM * D_DIM];
    __shared__ float sp[E_NUM];
    __shared__ int   sc[E_NUM];
    __shared__ float sz;

    int tid = threadIdx.x;
    for (int i = tid; i < E_NUM * D_DIM; i += 256) s_rw[i] = rw[i];
    if (tid < E_NUM) { sp[tid] = 0.0f; sc[tid] = 0; }
    if (tid == 0) sz = 0.0f;
    __syncthreads();

    int warp = tid >> 5;
    int lane = tid & 31;
    int t = blockIdx.x * 8 + warp;

    float acc[E_NUM];
#pragma unroll
    for (int e = 0; e < E_NUM; e++) acc[e] = 0.0f;

    const float* xr = x + (size_t)t * D_DIM;
    __half* xw = g_xh + (size_t)t * D_DIM;
    for (int d = lane; d < D_DIM; d += 32) {
        float xv = xr[d];
        xw[d] = __float2half_rn(xv);
#pragma unroll
        for (int e = 0; e < E_NUM; e++) acc[e] += xv * s_rw[e * D_DIM + d];
    }
#pragma unroll
    for (int e = 0; e < E_NUM; e++) {
#pragma unroll
        for (int off = 16; off > 0; off >>= 1)
            acc[e] += __shfl_xor_sync(0xFFFFFFFF, acc[e], off);
    }

    if (lane == 0) {
        float m = acc[0];
#pragma unroll
        for (int e = 1; e < E_NUM; e++) m = fmaxf(m, acc[e]);
        float p[E_NUM], s = 0.0f;
#pragma unroll
        for (int e = 0; e < E_NUM; e++) { p[e] = expf(acc[e] - m); s += p[e]; }
        float inv = 1.0f / s;
        float lse = m + logf(s);

        int i1 = 0;
#pragma unroll
        for (int e = 1; e < E_NUM; e++) if (acc[e] > acc[i1]) i1 = e;
        int i2 = (i1 == 0) ? 1 : 0;
#pragma unroll
        for (int e = 0; e < E_NUM; e++)
            if (e != i1 && acc[e] > acc[i2]) i2 = e;

        float p1 = p[i1] * inv, p2 = p[i2] * inv;
        float winv = 1.0f / (p1 + p2);
        g_sel[2 * t]      = i1;
        g_wsel[2 * t]     = p1 * winv;
        g_sel[2 * t + 1]  = i2;
        g_wsel[2 * t + 1] = p2 * winv;

#pragma unroll
        for (int e = 0; e < E_NUM; e++) atomicAdd(&sp[e], p[e] * inv);
        atomicAdd(&sz, lse * lse);
        atomicAdd(&sc[i1], 1);
        atomicAdd(&sc[i2], 1);
    }
    __syncthreads();
    if (tid < E_NUM) {
        atomicAdd(&g_psum[tid], sp[tid]);
        atomicAdd(&g_counts[tid], sc[tid]);
    }
    if (tid == 0) atomicAdd(&g_zsum, sz);
}

// ---------------- finalize losses + offsets scan ----------------
__global__ void finalize_kernel(float* out, int out_size) {
    if (threadIdx.x == 0 && blockIdx.x == 0) {
        int off = 0;
        for (int e = 0; e < E_NUM; e++) { g_offsets[e] = off; off += g_counts[e]; }
        float z = g_zsum / (float)T_TOK;
        float lb = 0.0f;
        for (int e = 0; e < E_NUM; e++)
            lb += ((float)g_counts[e] / (float)(T_TOK * K_TOP)) *
                  (g_psum[e] / (float)T_TOK);
        lb *= (float)E_NUM;
        out[out_size - 2] = z;
        out[out_size - 1] = lb;
    }
}

// ---------------- scatter into expert groups (+ inverse map) ---------------
__global__ void scatter_kernel() {
    int s = blockIdx.x * blockDim.x + threadIdx.x;
    if (s >= NSLOT) return;
    int e = g_sel[s];
    int pos = g_offsets[e] + atomicAdd(&g_fill[e], 1);
    g_slot_token[pos] = s >> 1;
    g_pos[s] = pos;
}

// ---------------- gather: out[t] = w0*y[p0] + w1*y[p1] ---------------------
__global__ __launch_bounds__(256) void gather_kernel(float* __restrict__ out) {
    int t = blockIdx.x;
    int p0 = g_pos[2 * t], p1 = g_pos[2 * t + 1];
    float w0 = g_wsel[2 * t], w1 = g_wsel[2 * t + 1];
    const float4* y0 = (const float4*)(g_y + (size_t)p0 * D_DIM);
    const float4* y1 = (const float4*)(g_y + (size_t)p1 * D_DIM);
    float4* op = (float4*)(out + (size_t)t * D_DIM);
    int i = threadIdx.x;
    float4 a = y0[i], b = y1[i];
    float4 r;
    r.x = w0 * a.x + w1 * b.x;
    r.y = w0 * a.y + w1 * b.y;
    r.z = w0 * a.z + w1 * b.z;
    r.w = w0 * a.w + w1 * b.w;
    op[i] = r;
}

// ============== fp16 tensor-core grouped GEMMs (R10 loop) ==================
#define BM 128
#define BN 128
#define BKB 32
#define AKP 40    // A row stride (half): 80 B
#define BNP 136   // B row stride (half): 272 B

__device__ __forceinline__ float gelu_exact(float v) {
    return 0.5f * v * (1.0f + erff(v * 0.70710678118654752f));
}

__device__ __forceinline__ void mma_f16(
    float& c0, float& c1, float& c2, float& c3,
    uint32_t a0, uint32_t a1, uint32_t a2, uint32_t a3,
    uint32_t b0, uint32_t b1)
{
    asm volatile(
        "mma.sync.aligned.m16n8k16.row.col.f32.f16.f16.f32 "
        "{%0,%1,%2,%3}, {%4,%5,%6,%7}, {%8,%9}, {%0,%1,%2,%3};"
        : "+f"(c0), "+f"(c1), "+f"(c2), "+f"(c3)
        : "r"(a0), "r"(a1), "r"(a2), "r"(a3), "r"(b0), "r"(b1));
}

__device__ __forceinline__ void ldsm_x4(uint32_t* r, const void* p) {
    uint32_t addr = (uint32_t)__cvta_generic_to_shared(p);
    asm volatile("ldmatrix.sync.aligned.m8n8.x4.shared.b16 {%0,%1,%2,%3}, [%4];"
                 : "=r"(r[0]), "=r"(r[1]), "=r"(r[2]), "=r"(r[3]) : "r"(addr));
}
__device__ __forceinline__ void ldsm_x4_trans(uint32_t* r, const void* p) {
    uint32_t addr = (uint32_t)__cvta_generic_to_shared(p);
    asm volatile("ldmatrix.sync.aligned.m8n8.x4.trans.shared.b16 {%0,%1,%2,%3}, [%4];"
                 : "=r"(r[0]), "=r"(r[1]), "=r"(r[2]), "=r"(r[3]) : "r"(addr));
}

// GEMM1: h = gelu( x_gathered @ w1_e )
__global__ __launch_bounds__(256, 2) void gemm1_kernel() {
    int e = blockIdx.z;
    int base = g_offsets[e];
    int cnt  = g_counts[e];
    int m0   = blockIdx.y * BM;
    if (m0 >= cnt) return;
    int n0   = blockIdx.x * BN;

    __shared__ __half Ah[BM][AKP];
    __shared__ __half Bh[BKB][BNP];

    int tid  = threadIdx.x;
    int lane = tid & 31;
    int warp = tid >> 5;
    int group = lane >> 2;
    int tid4  = lane & 3;
    int wm = (warp & 1) * 64;
    int wn = (warp >> 1) * 32;
    int lrow = lane & 15;
    int lcol = (lane >> 4) << 3;

    int am = tid >> 1;
    int kb = (tid & 1) * 16;
    int arow = base + m0 + am;
    int tok  = g_slot_token[arow < NSLOT ? arow : NSLOT - 1];
    const __half* aph = g_xh + (size_t)tok * D_DIM + kb;

    int bkr = tid >> 3;
    int bnc = (tid & 7) * 16;
    size_t bbase = (size_t)e * FF_DIM + n0 + bnc;

    float acc[4][4][4];
#pragma unroll
    for (int mi = 0; mi < 4; mi++)
#pragma unroll
        for (int ni = 0; ni < 4; ni++)
#pragma unroll
            for (int c = 0; c < 4; c++) acc[mi][ni][c] = 0.0f;

    uint4 pah0 = *(const uint4*)(aph + 0);
    uint4 pah1 = *(const uint4*)(aph + 8);
    uint4 pbh0 = *(const uint4*)(g_w1h + (size_t)bkr * W1_LD + bbase);
    uint4 pbh1 = *(const uint4*)(g_w1h + (size_t)bkr * W1_LD + bbase + 8);
    *(uint4*)&Ah[am][kb]     = pah0; *(uint4*)&Ah[am][kb + 8]   = pah1;
    *(uint4*)&Bh[bkr][bnc]   = pbh0; *(uint4*)&Bh[bkr][bnc + 8] = pbh1;
    __syncthreads();

    for (int kt = 0; kt < D_DIM; kt += BKB) {
        bool more = (kt + BKB) < D_DIM;
        if (more) {
            pah0 = *(const uint4*)(aph + kt + BKB + 0);
            pah1 = *(const uint4*)(aph + kt + BKB + 8);
            pbh0 = *(const uint4*)(g_w1h + (size_t)(kt + BKB + bkr) * W1_LD + bbase);
            pbh1 = *(const uint4*)(g_w1h + (size_t)(kt + BKB + bkr) * W1_LD + bbase + 8);
        }
#pragma unroll
        for (int ks = 0; ks < 2; ks++) {
            int k0 = ks * 16;
            uint32_t ah[4][4], bh[4][2];
#pragma unroll
            for (int mi = 0; mi < 4; mi++)
                ldsm_x4(ah[mi], &Ah[wm + mi * 16 + lrow][k0 + lcol]);
#pragma unroll
            for (int nh = 0; nh < 2; nh++) {
                uint32_t r[4];
                ldsm_x4_trans(r, &Bh[k0 + lrow][wn + nh * 16 + lcol]);
                bh[2 * nh][0] = r[0]; bh[2 * nh][1] = r[1];
                bh[2 * nh + 1][0] = r[2]; bh[2 * nh + 1][1] = r[3];
            }
#pragma unroll
            for (int mi = 0; mi < 4; mi++)
#pragma unroll
                for (int ni = 0; ni < 4; ni++)
                    mma_f16(acc[mi][ni][0], acc[mi][ni][1], acc[mi][ni][2], acc[mi][ni][3],
                            ah[mi][0], ah[mi][1], ah[mi][2], ah[mi][3],
                            bh[ni][0], bh[ni][1]);
        }
        __syncthreads();
        if (more) {
            *(uint4*)&Ah[am][kb]      = pah0; *(uint4*)&Ah[am][kb + 8]   = pah1;
            *(uint4*)&Bh[bkr][bnc]    = pbh0; *(uint4*)&Bh[bkr][bnc + 8] = pbh1;
        }
        __syncthreads();
    }

    // epilogue: gelu -> fp16 -> g_hh
#pragma unroll
    for (int mi = 0; mi < 4; mi++) {
        int rm0 = m0 + wm + mi * 16 + group;
        int rm1 = rm0 + 8;
#pragma unroll
        for (int ni = 0; ni < 4; ni++) {
            int n = n0 + wn + ni * 8 + tid4 * 2;
            if (rm0 < cnt) {
                __half h0 = __float2half_rn(gelu_exact(acc[mi][ni][0]));
                __half h1 = __float2half_rn(gelu_exact(acc[mi][ni][1]));
                *(__half2*)(g_hh + (size_t)(base + rm0) * FF_DIM + n) =
                    __halves2half2(h0, h1);
            }
            if (rm1 < cnt) {
                __half h0 = __float2half_rn(gelu_exact(acc[mi][ni][2]));
                __half h1 = __float2half_rn(gelu_exact(acc[mi][ni][3]));
                *(__half2*)(g_hh + (size_t)(base + rm1) * FF_DIM + n) =
                    __halves2half2(h0, h1);
            }
        }
    }
}

// GEMM2: y[row] = h[row] @ w2_e   (plain streaming stores, no atomics)
__global__ __launch_bounds__(256, 2) void gemm2_kernel() {
    int e = blockIdx.z;
    int base = g_offsets[e];
    int cnt  = g_counts[e];
    int m0   = blockIdx.y * BM;
    if (m0 >= cnt) return;
    int n0   = blockIdx.x * BN;

    __shared__ __half Ah[BM][AKP];
    __shared__ __half Bh[BKB][BNP];

    int tid  = threadIdx.x;
    int lane = tid & 31;
    int warp = tid >> 5;
    int group = lane >> 2;
    int tid4  = lane & 3;
    int wm = (warp & 1) * 64;
    int wn = (warp >> 1) * 32;
    int lrow = lane & 15;
    int lcol = (lane >> 4) << 3;

    int am = tid >> 1;
    int kb = (tid & 1) * 16;
    int arow = base + m0 + am;
    if (arow >= NSLOT) arow = NSLOT - 1;
    const __half* aph = g_hh + (size_t)arow * FF_DIM + kb;

    int bkr = tid >> 3;
    int bnc = (tid & 7) * 16;
    size_t bbase = (size_t)e * FF_DIM * D_DIM + n0 + bnc;

    float acc[4][4][4];
#pragma unroll
    for (int mi = 0; mi < 4; mi++)
#pragma unroll
        for (int ni = 0; ni < 4; ni++)
#pragma unroll
            for (int c = 0; c < 4; c++) acc[mi][ni][c] = 0.0f;

    uint4 pah0 = *(const uint4*)(aph + 0);
    uint4 pah1 = *(const uint4*)(aph + 8);
    uint4 pbh0 = *(const uint4*)(g_w2h + (size_t)bkr * D_DIM + bbase);
    uint4 pbh1 = *(const uint4*)(g_w2h + (size_t)bkr * D_DIM + bbase + 8);
    *(uint4*)&Ah[am][kb]     = pah0; *(uint4*)&Ah[am][kb + 8]   = pah1;
    *(uint4*)&Bh[bkr][bnc]   = pbh0; *(uint4*)&Bh[bkr][bnc + 8] = pbh1;
    __syncthreads();

    for (int kt = 0; kt < FF_DIM; kt += BKB) {
        bool more = (kt + BKB) < FF_DIM;
        if (more) {
            pah0 = *(const uint4*)(aph + kt + BKB + 0);
            pah1 = *(const uint4*)(aph + kt + BKB + 8);
            pbh0 = *(const uint4*)(g_w2h + (size_t)(kt + BKB + bkr) * D_DIM + bbase);
            pbh1 = *(const uint4*)(g_w2h + (size_t)(kt + BKB + bkr) * D_DIM + bbase + 8);
        }
#pragma unroll
        for (int ks = 0; ks < 2; ks++) {
            int k0 = ks * 16;
            uint32_t ah[4][4], bh[4][2];
#pragma unroll
            for (int mi = 0; mi < 4; mi++)
                ldsm_x4(ah[mi], &Ah[wm + mi * 16 + lrow][k0 + lcol]);
#pragma unroll
            for (int nh = 0; nh < 2; nh++) {
                uint32_t r[4];
                ldsm_x4_trans(r, &Bh[k0 + lrow][wn + nh * 16 + lcol]);
                bh[2 * nh][0] = r[0]; bh[2 * nh][1] = r[1];
                bh[2 * nh + 1][0] = r[2]; bh[2 * nh + 1][1] = r[3];
            }
#pragma unroll
            for (int mi = 0; mi < 4; mi++)
#pragma unroll
                for (int ni = 0; ni < 4; ni++)
                    mma_f16(acc[mi][ni][0], acc[mi][ni][1], acc[mi][ni][2], acc[mi][ni][3],
                            ah[mi][0], ah[mi][1], ah[mi][2], ah[mi][3],
                            bh[ni][0], bh[ni][1]);
        }
        __syncthreads();
        if (more) {
            *(uint4*)&Ah[am][kb]      = pah0; *(uint4*)&Ah[am][kb + 8]   = pah1;
            *(uint4*)&Bh[bkr][bnc]    = pbh0; *(uint4*)&Bh[bkr][bnc + 8] = pbh1;
        }
        __syncthreads();
    }

    // epilogue: plain stores to per-slot buffer
#pragma unroll
    for (int mi = 0; mi < 4; mi++) {
        int rm0 = m0 + wm + mi * 16 + group;
        int rm1 = rm0 + 8;
#pragma unroll
        for (int ni = 0; ni < 4; ni++) {
            int n = n0 + wn + ni * 8 + tid4 * 2;
            if (rm0 < cnt) {
                float2 v = make_float2(acc[mi][ni][0], acc[mi][ni][1]);
                *(float2*)(g_y + (size_t)(base + rm0) * D_DIM + n) = v;
            }
            if (rm1 < cnt) {
                float2 v = make_float2(acc[mi][ni][2], acc[mi][ni][3]);
                *(float2*)(g_y + (size_t)(base + rm1) * D_DIM + n) = v;
            }
        }
    }
}

// ---------------- launcher ----------------
extern "C" void kernel_launch(void* const* d_in, const int* in_sizes, int n_in,
                              void* d_out, int out_size) {
    const float* x  = (const float*)d_in[0];
    const float* rw = (const float*)d_in[1];
    const float* w1 = (const float*)d_in[2];
    const float* w2 = (const float*)d_in[3];
    float* out = (float*)d_out;

    init_kernel<<<1, 64>>>();
    cvt_w_kernel<<<8192, 256>>>(w1, w2);
    router_kernel<<<T_TOK / 8, 256>>>(x, rw);
    finalize_kernel<<<1, 32>>>(out, out_size);
    scatter_kernel<<<NSLOT / 256, 256>>>();

    dim3 g1(FF_DIM / BN, T_TOK / BM, E_NUM);
    gemm1_kernel<<<g1, 256>>>();
    dim3 g2(D_DIM / BN, T_TOK / BM, E_NUM);
    gemm2_kernel<<<g2, 256>>>();
    gather_kernel<<<T_TOK, 256>>>(out);
}

// round 14
// speedup vs baseline: 1.0982x; 1.0293x over previous
#include <cuda_runtime.h>
#include <cuda_fp16.h>
#include <math.h>
#include <stdint.h>

// Problem constants
#define T_TOK 8192
#define D_DIM 1024
#define FF_DIM 2048
#define E_NUM 8
#define K_TOP 2
#define NSLOT (T_TOK * K_TOP)
#define W1_LD (E_NUM * FF_DIM)

// ---------------- scratch (device globals) ---------------------------------
__device__ __half g_xh[(size_t)T_TOK * D_DIM];
__device__ __half g_w1h[(size_t)D_DIM * W1_LD];
__device__ __half g_w2h[(size_t)E_NUM * FF_DIM * D_DIM];
__device__ __half g_hh[(size_t)NSLOT * FF_DIM];
__device__ float  g_y[(size_t)NSLOT * D_DIM];

__device__ int   g_sel[NSLOT];
__device__ float g_wsel[NSLOT];
__device__ int   g_slot_token[NSLOT];
__device__ int   g_pos[NSLOT];
__device__ int   g_counts[E_NUM];
__device__ int   g_offsets[E_NUM];
__device__ int   g_fill[E_NUM];
__device__ float g_psum[E_NUM];
__device__ float g_zsum;

// ---------------- merged weight convert (f32 -> fp16) ----------------------
__global__ void cvt_w_kernel(const float* __restrict__ w1,
                             const float* __restrict__ w2) {
    const int n1 = (D_DIM * W1_LD) / 4;
    const int n2 = (E_NUM * FF_DIM * D_DIM) / 4;
    for (int i = blockIdx.x * blockDim.x + threadIdx.x; i < n1 + n2;
         i += gridDim.x * blockDim.x) {
        float4 v;
        if (i < n1) v = ((const float4*)w1)[i];
        else        v = ((const float4*)w2)[i - n1];
        __half h[4];
        h[0] = __float2half_rn(v.x); h[1] = __float2half_rn(v.y);
        h[2] = __float2half_rn(v.z); h[3] = __float2half_rn(v.w);
        if (i < n1) ((uint2*)g_w1h)[i]      = *(uint2*)h;
        else        ((uint2*)g_w2h)[i - n1] = *(uint2*)h;
    }
}

// ---------------- init accumulators ----------------
__global__ void init_kernel() {
    int t = threadIdx.x;
    if (t < E_NUM) { g_counts[t] = 0; g_fill[t] = 0; g_psum[t] = 0.0f; }
    if (t == 0) g_zsum = 0.0f;
}

// ---------------- router (vectorized; also emits fp16 x) -------------------
__global__ __launch_bounds__(256) void router_kernel(
    const float* __restrict__ x, const float* __restrict__ rw)
{
    __shared__ float s_rw[E_NUM * D_DIM];
    __shared__ float sp[E_NUM];
    __shared__ int   sc[E_NUM];
    __shared__ float sz;

    int tid = threadIdx.x;
    for (int i = tid; i < (E_NUM * D_DIM) / 4; i += 256)
        ((float4*)s_rw)[i] = ((const float4*)rw)[i];
    if (tid < E_NUM) { sp[tid] = 0.0f; sc[tid] = 0; }
    if (tid == 0) sz = 0.0f;
    __syncthreads();

    int warp = tid >> 5;
    int lane = tid & 31;
    int t = blockIdx.x * 8 + warp;

    float acc[E_NUM];
#pragma unroll
    for (int e = 0; e < E_NUM; e++) acc[e] = 0.0f;

    const float4* xr4 = (const float4*)(x + (size_t)t * D_DIM);
    __half2* xw2 = (__half2*)(g_xh + (size_t)t * D_DIM);
#pragma unroll
    for (int i = 0; i < 8; i++) {
        int d4 = lane + i * 32;                 // float4 index, 0..255
        float4 xv = xr4[d4];
        xw2[2 * d4 + 0] = __floats2half2_rn(xv.x, xv.y);
        xw2[2 * d4 + 1] = __floats2half2_rn(xv.z, xv.w);
#pragma unroll
        for (int e = 0; e < E_NUM; e++) {
            float4 w = ((const float4*)(s_rw + e * D_DIM))[d4];
            acc[e] += xv.x * w.x + xv.y * w.y + xv.z * w.z + xv.w * w.w;
        }
    }
#pragma unroll
    for (int e = 0; e < E_NUM; e++) {
#pragma unroll
        for (int off = 16; off > 0; off >>= 1)
            acc[e] += __shfl_xor_sync(0xFFFFFFFF, acc[e], off);
    }

    if (lane == 0) {
        float m = acc[0];
#pragma unroll
        for (int e = 1; e < E_NUM; e++) m = fmaxf(m, acc[e]);
        float p[E_NUM], s = 0.0f;
#pragma unroll
        for (int e = 0; e < E_NUM; e++) { p[e] = expf(acc[e] - m); s += p[e]; }
        float inv = 1.0f / s;
        float lse = m + logf(s);

        int i1 = 0;
#pragma unroll
        for (int e = 1; e < E_NUM; e++) if (acc[e] > acc[i1]) i1 = e;
        int i2 = (i1 == 0) ? 1 : 0;
#pragma unroll
        for (int e = 0; e < E_NUM; e++)
            if (e != i1 && acc[e] > acc[i2]) i2 = e;

        float p1 = p[i1] * inv, p2 = p[i2] * inv;
        float winv = 1.0f / (p1 + p2);
        g_sel[2 * t]      = i1;
        g_wsel[2 * t]     = p1 * winv;
        g_sel[2 * t + 1]  = i2;
        g_wsel[2 * t + 1] = p2 * winv;

#pragma unroll
        for (int e = 0; e < E_NUM; e++) atomicAdd(&sp[e], p[e] * inv);
        atomicAdd(&sz, lse * lse);
        atomicAdd(&sc[i1], 1);
        atomicAdd(&sc[i2], 1);
    }
    __syncthreads();
    if (tid < E_NUM) {
        atomicAdd(&g_psum[tid], sp[tid]);
        atomicAdd(&g_counts[tid], sc[tid]);
    }
    if (tid == 0) atomicAdd(&g_zsum, sz);
}

// ---------------- finalize losses + offsets scan ----------------
__global__ void finalize_kernel(float* out, int out_size) {
    if (threadIdx.x == 0 && blockIdx.x == 0) {
        int off = 0;
        for (int e = 0; e < E_NUM; e++) { g_offsets[e] = off; off += g_counts[e]; }
        float z = g_zsum / (float)T_TOK;
        float lb = 0.0f;
        for (int e = 0; e < E_NUM; e++)
            lb += ((float)g_counts[e] / (float)(T_TOK * K_TOP)) *
                  (g_psum[e] / (float)T_TOK);
        lb *= (float)E_NUM;
        out[out_size - 2] = z;
        out[out_size - 1] = lb;
    }
}

// ---------------- scatter into expert groups (+ inverse map) ---------------
__global__ void scatter_kernel() {
    int s = blockIdx.x * blockDim.x + threadIdx.x;
    if (s >= NSLOT) return;
    int e = g_sel[s];
    int pos = g_offsets[e] + atomicAdd(&g_fill[e], 1);
    g_slot_token[pos] = s >> 1;
    g_pos[s] = pos;
}

// ---------------- gather: out[t] = w0*y[p0] + w1*y[p1] ---------------------
__global__ __launch_bounds__(256) void gather_kernel(float* __restrict__ out) {
    int t = blockIdx.x;
    int p0 = g_pos[2 * t], p1 = g_pos[2 * t + 1];
    float w0 = g_wsel[2 * t], w1 = g_wsel[2 * t + 1];
    const float4* y0 = (const float4*)(g_y + (size_t)p0 * D_DIM);
    const float4* y1 = (const float4*)(g_y + (size_t)p1 * D_DIM);
    float4* op = (float4*)(out + (size_t)t * D_DIM);
    int i = threadIdx.x;
    float4 a = y0[i], b = y1[i];
    float4 r;
    r.x = w0 * a.x + w1 * b.x;
    r.y = w0 * a.y + w1 * b.y;
    r.z = w0 * a.z + w1 * b.z;
    r.w = w0 * a.w + w1 * b.w;
    op[i] = r;
}

// ============== fp16 tensor-core grouped GEMMs (cp.async 2-stage) ==========
#define BM 128
#define BN 128
#define BKB 32
#define AKP 40    // A row stride (half): 80 B (16B-aligned)
#define BNP 136   // B row stride (half): 272 B (16B-aligned)

__device__ __forceinline__ float gelu_exact(float v) {
    return 0.5f * v * (1.0f + erff(v * 0.70710678118654752f));
}

__device__ __forceinline__ void mma_f16(
    float& c0, float& c1, float& c2, float& c3,
    uint32_t a0, uint32_t a1, uint32_t a2, uint32_t a3,
    uint32_t b0, uint32_t b1)
{
    asm volatile(
        "mma.sync.aligned.m16n8k16.row.col.f32.f16.f16.f32 "
        "{%0,%1,%2,%3}, {%4,%5,%6,%7}, {%8,%9}, {%0,%1,%2,%3};"
        : "+f"(c0), "+f"(c1), "+f"(c2), "+f"(c3)
        : "r"(a0), "r"(a1), "r"(a2), "r"(a3), "r"(b0), "r"(b1));
}

__device__ __forceinline__ void ldsm_x4(uint32_t* r, const void* p) {
    uint32_t addr = (uint32_t)__cvta_generic_to_shared(p);
    asm volatile("ldmatrix.sync.aligned.m8n8.x4.shared.b16 {%0,%1,%2,%3}, [%4];"
                 : "=r"(r[0]), "=r"(r[1]), "=r"(r[2]), "=r"(r[3]) : "r"(addr));
}
__device__ __forceinline__ void ldsm_x4_trans(uint32_t* r, const void* p) {
    uint32_t addr = (uint32_t)__cvta_generic_to_shared(p);
    asm volatile("ldmatrix.sync.aligned.m8n8.x4.trans.shared.b16 {%0,%1,%2,%3}, [%4];"
                 : "=r"(r[0]), "=r"(r[1]), "=r"(r[2]), "=r"(r[3]) : "r"(addr));
}

#define CPA16(s, g) \
    asm volatile("cp.async.cg.shared.global [%0], [%1], 16;" :: "r"(s), "l"(g))
#define CP_COMMIT() asm volatile("cp.async.commit_group;" ::: "memory")
#define CP_WAIT0()  asm volatile("cp.async.wait_group 0;" ::: "memory")

#define MMA_STAGE(AH, BH)                                                      \
    do {                                                                       \
        _Pragma("unroll")                                                      \
        for (int ks = 0; ks < 2; ks++) {                                       \
            int k0 = ks * 16;                                                  \
            uint32_t ah[4][4], bh[4][2];                                       \
            _Pragma("unroll")                                                  \
            for (int mi = 0; mi < 4; mi++)                                     \
                ldsm_x4(ah[mi], &AH[wm + mi * 16 + lrow][k0 + lcol]);          \
            _Pragma("unroll")                                                  \
            for (int nh = 0; nh < 2; nh++) {                                   \
                uint32_t r[4];                                                 \
                ldsm_x4_trans(r, &BH[k0 + lrow][wn + nh * 16 + lcol]);         \
                bh[2 * nh][0] = r[0]; bh[2 * nh][1] = r[1];                    \
                bh[2 * nh + 1][0] = r[2]; bh[2 * nh + 1][1] = r[3];            \
            }                                                                  \
            _Pragma("unroll")                                                  \
            for (int mi = 0; mi < 4; mi++)                                     \
                _Pragma("unroll")                                              \
                for (int ni = 0; ni < 4; ni++)                                 \
                    mma_f16(acc[mi][ni][0], acc[mi][ni][1],                    \
                            acc[mi][ni][2], acc[mi][ni][3],                    \
                            ah[mi][0], ah[mi][1], ah[mi][2], ah[mi][3],        \
                            bh[ni][0], bh[ni][1]);                             \
        }                                                                      \
    } while (0)

// GEMM1: h = gelu( x_gathered @ w1_e )
__global__ __launch_bounds__(256, 2) void gemm1_kernel() {
    int e = blockIdx.z;
    int base = g_offsets[e];
    int cnt  = g_counts[e];
    int m0   = blockIdx.y * BM;
    if (m0 >= cnt) return;
    int n0   = blockIdx.x * BN;

    __shared__ __half Ah0[BM][AKP], Ah1[BM][AKP];
    __shared__ __half Bh0[BKB][BNP], Bh1[BKB][BNP];

    int tid  = threadIdx.x;
    int lane = tid & 31;
    int warp = tid >> 5;
    int group = lane >> 2;
    int tid4  = lane & 3;
    int wm = (warp & 1) * 64;
    int wn = (warp >> 1) * 32;
    int lrow = lane & 15;
    int lcol = (lane >> 4) << 3;

    int am = tid >> 1;
    int kb = (tid & 1) * 16;
    int arow = base + m0 + am;
    int tok  = g_slot_token[arow < NSLOT ? arow : NSLOT - 1];
    const __half* aph = g_xh + (size_t)tok * D_DIM + kb;

    int bkr = tid >> 3;
    int bnc = (tid & 7) * 16;
    const __half* bph = g_w1h + (size_t)e * FF_DIM + n0 + bnc;  // row k: bph + k*W1_LD

    uint32_t sA0 = (uint32_t)__cvta_generic_to_shared(&Ah0[am][kb]);
    uint32_t sA1 = (uint32_t)__cvta_generic_to_shared(&Ah1[am][kb]);
    uint32_t sB0 = (uint32_t)__cvta_generic_to_shared(&Bh0[bkr][bnc]);
    uint32_t sB1 = (uint32_t)__cvta_generic_to_shared(&Bh1[bkr][bnc]);

    float acc[4][4][4];
#pragma unroll
    for (int mi = 0; mi < 4; mi++)
#pragma unroll
        for (int ni = 0; ni < 4; ni++)
#pragma unroll
            for (int c = 0; c < 4; c++) acc[mi][ni][c] = 0.0f;

    // prologue: stage 0 <- k[0,32)
    CPA16(sA0,      aph + 0);
    CPA16(sA0 + 16, aph + 8);
    CPA16(sB0,      bph + (size_t)bkr * W1_LD + 0);
    CPA16(sB0 + 16, bph + (size_t)bkr * W1_LD + 8);
    CP_COMMIT(); CP_WAIT0();
    __syncthreads();

#pragma unroll 1
    for (int kt = 0; kt < D_DIM; kt += 2 * BKB) {
        // stage1 <- kt+32 (always valid: D_DIM % 64 == 0)
        CPA16(sA1,      aph + kt + BKB + 0);
        CPA16(sA1 + 16, aph + kt + BKB + 8);
        CPA16(sB1,      bph + (size_t)(kt + BKB + bkr) * W1_LD + 0);
        CPA16(sB1 + 16, bph + (size_t)(kt + BKB + bkr) * W1_LD + 8);
        CP_COMMIT();
        MMA_STAGE(Ah0, Bh0);
        CP_WAIT0();
        __syncthreads();
        bool more = (kt + 2 * BKB) < D_DIM;
        if (more) {
            CPA16(sA0,      aph + kt + 2 * BKB + 0);
            CPA16(sA0 + 16, aph + kt + 2 * BKB + 8);
            CPA16(sB0,      bph + (size_t)(kt + 2 * BKB + bkr) * W1_LD + 0);
            CPA16(sB0 + 16, bph + (size_t)(kt + 2 * BKB + bkr) * W1_LD + 8);
            CP_COMMIT();
        }
        MMA_STAGE(Ah1, Bh1);
        CP_WAIT0();
        __syncthreads();
    }

    // epilogue: gelu -> fp16 -> g_hh
#pragma unroll
    for (int mi = 0; mi < 4; mi++) {
        int rm0 = m0 + wm + mi * 16 + group;
        int rm1 = rm0 + 8;
#pragma unroll
        for (int ni = 0; ni < 4; ni++) {
            int n = n0 + wn + ni * 8 + tid4 * 2;
            if (rm0 < cnt) {
                __half h0 = __float2half_rn(gelu_exact(acc[mi][ni][0]));
                __half h1 = __float2half_rn(gelu_exact(acc[mi][ni][1]));
                *(__half2*)(g_hh + (size_t)(base + rm0) * FF_DIM + n) =
                    __halves2half2(h0, h1);
            }
            if (rm1 < cnt) {
                __half h0 = __float2half_rn(gelu_exact(acc[mi][ni][2]));
                __half h1 = __float2half_rn(gelu_exact(acc[mi][ni][3]));
                *(__half2*)(g_hh + (size_t)(base + rm1) * FF_DIM + n) =
                    __halves2half2(h0, h1);
            }
        }
    }
}

// GEMM2: y[row] = h[row] @ w2_e   (streaming stores)
__global__ __launch_bounds__(256, 2) void gemm2_kernel() {
    int e = blockIdx.z;
    int base = g_offsets[e];
    int cnt  = g_counts[e];
    int m0   = blockIdx.y * BM;
    if (m0 >= cnt) return;
    int n0   = blockIdx.x * BN;

    __shared__ __half Ah0[BM][AKP], Ah1[BM][AKP];
    __shared__ __half Bh0[BKB][BNP], Bh1[BKB][BNP];

    int tid  = threadIdx.x;
    int lane = tid & 31;
    int warp = tid >> 5;
    int group = lane >> 2;
    int tid4  = lane & 3;
    int wm = (warp & 1) * 64;
    int wn = (warp >> 1) * 32;
    int lrow = lane & 15;
    int lcol = (lane >> 4) << 3;

    int am = tid >> 1;
    int kb = (tid & 1) * 16;
    int arow = base + m0 + am;
    if (arow >= NSLOT) arow = NSLOT - 1;
    const __half* aph = g_hh + (size_t)arow * FF_DIM + kb;

    int bkr = tid >> 3;
    int bnc = (tid & 7) * 16;
    const __half* bph = g_w2h + (size_t)e * FF_DIM * D_DIM + n0 + bnc;  // row k: + k*D_DIM

    uint32_t sA0 = (uint32_t)__cvta_generic_to_shared(&Ah0[am][kb]);
    uint32_t sA1 = (uint32_t)__cvta_generic_to_shared(&Ah1[am][kb]);
    uint32_t sB0 = (uint32_t)__cvta_generic_to_shared(&Bh0[bkr][bnc]);
    uint32_t sB1 = (uint32_t)__cvta_generic_to_shared(&Bh1[bkr][bnc]);

    float acc[4][4][4];
#pragma unroll
    for (int mi = 0; mi < 4; mi++)
#pragma unroll
        for (int ni = 0; ni < 4; ni++)
#pragma unroll
            for (int c = 0; c < 4; c++) acc[mi][ni][c] = 0.0f;

    CPA16(sA0,      aph + 0);
    CPA16(sA0 + 16, aph + 8);
    CPA16(sB0,      bph + (size_t)bkr * D_DIM + 0);
    CPA16(sB0 + 16, bph + (size_t)bkr * D_DIM + 8);
    CP_COMMIT(); CP_WAIT0();
    __syncthreads();

#pragma unroll 1
    for (int kt = 0; kt < FF_DIM; kt += 2 * BKB) {
        CPA16(sA1,      aph + kt + BKB + 0);
        CPA16(sA1 + 16, aph + kt + BKB + 8);
        CPA16(sB1,      bph + (size_t)(kt + BKB + bkr) * D_DIM + 0);
        CPA16(sB1 + 16, bph + (size_t)(kt + BKB + bkr) * D_DIM + 8);
        CP_COMMIT();
        MMA_STAGE(Ah0, Bh0);
        CP_WAIT0();
        __syncthreads();
        bool more = (kt + 2 * BKB) < FF_DIM;
        if (more) {
            CPA16(sA0,      aph + kt + 2 * BKB + 0);
            CPA16(sA0 + 16, aph + kt + 2 * BKB + 8);
            CPA16(sB0,      bph + (size_t)(kt + 2 * BKB + bkr) * D_DIM + 0);
            CPA16(sB0 + 16, bph + (size_t)(kt + 2 * BKB + bkr) * D_DIM + 8);
            CP_COMMIT();
        }
        MMA_STAGE(Ah1, Bh1);
        CP_WAIT0();
        __syncthreads();
    }

    // epilogue: plain stores to per-slot buffer
#pragma unroll
    for (int mi = 0; mi < 4; mi++) {
        int rm0 = m0 + wm + mi * 16 + group;
        int rm1 = rm0 + 8;
#pragma unroll
        for (int ni = 0; ni < 4; ni++) {
            int n = n0 + wn + ni * 8 + tid4 * 2;
            if (rm0 < cnt) {
                float2 v = make_float2(acc[mi][ni][0], acc[mi][ni][1]);
                *(float2*)(g_y + (size_t)(base + rm0) * D_DIM + n) = v;
            }
            if (rm1 < cnt) {
                float2 v = make_float2(acc[mi][ni][2], acc[mi][ni][3]);
                *(float2*)(g_y + (size_t)(base + rm1) * D_DIM + n) = v;
            }
        }
    }
}

// ---------------- launcher ----------------
extern "C" void kernel_launch(void* const* d_in, const int* in_sizes, int n_in,
                              void* d_out, int out_size) {
    const float* x  = (const float*)d_in[0];
    const float* rw = (const float*)d_in[1];
    const float* w1 = (const float*)d_in[2];
    const float* w2 = (const float*)d_in[3];
    float* out = (float*)d_out;

    init_kernel<<<1, 64>>>();
    cvt_w_kernel<<<8192, 256>>>(w1, w2);
    router_kernel<<<T_TOK / 8, 256>>>(x, rw);
    finalize_kernel<<<1, 32>>>(out, out_size);
    scatter_kernel<<<NSLOT / 256, 256>>>();

    dim3 g1(FF_DIM / BN, T_TOK / BM, E_NUM);
    gemm1_kernel<<<g1, 256>>>();
    dim3 g2(D_DIM / BN, T_TOK / BM, E_NUM);
    gemm2_kernel<<<g2, 256>>>();
    gather_kernel<<<T_TOK, 256>>>(out);
}